// round 2
// baseline (speedup 1.0000x reference)
#include <cuda_runtime.h>
#include <math.h>

// Problem constants
#define AEMB   16
#define DIN    480
#define OUT0D  224     // W1_l0 last-dim stride (only k<128 live)
#define M0     128
#define BM     128     // nodes per CTA
#define NTH    256
#define KC     64      // K-chunk (4 i x 16 a)
#define NCHUNK 32      // 2048 / KC

// Shared memory layout (floats)
#define X0_PITCH 129
#define AS_PITCH 17
#define AS_OFF   (BM * X0_PITCH)                  // 16512
#define ZAD_OFF  (AS_OFF + BM * AS_PITCH)         // +2176  = 18688
#define WB_OFF   (ZAD_OFF + KC * BM * 2)          // +16384 = 35072
#define MID_OFF  (WB_OFF + KC * 128)              // +8192  = 43264
#define SMEM_FLOATS (MID_OFF + BM * AEMB)         // 45312
#define SMEM_BYTES  (SMEM_FLOATS * 4)             // 181248

typedef unsigned long long ull;

__device__ __forceinline__ ull pk2(float lo, float hi) {
    ull d; asm("mov.b64 %0, {%1, %2};" : "=l"(d) : "f"(lo), "f"(hi)); return d;
}
__device__ __forceinline__ ull fma2(ull a, ull b, ull c) {
    ull d; asm("fma.rn.f32x2 %0, %1, %2, %3;" : "=l"(d) : "l"(a), "l"(b), "l"(c)); return d;
}
__device__ __forceinline__ ull mul2(ull a, ull b) {
    ull d; asm("mul.rn.f32x2 %0, %1, %2;" : "=l"(d) : "l"(a), "l"(b)); return d;
}
__device__ __forceinline__ void upk2(ull v, float& lo, float& hi) {
    asm("mov.b64 {%0, %1}, %2;" : "=f"(lo), "=f"(hi) : "l"(v));
}
__device__ __forceinline__ float silu_f(float x) { return x / (1.0f + __expf(-x)); }

__global__ void __launch_bounds__(NTH, 1)
tp_head_kernel(const float* __restrict__ nv,   // node_vec   [N,480]
               const float* __restrict__ ae,   // embedding  [N,16]
               const float* __restrict__ W1,   // W1_l0      [128,16,224]
               const float* __restrict__ b1,   // [224]
               const float* __restrict__ W2,   // [128,16,16]
               const float* __restrict__ b2,   // [16]
               const float* __restrict__ W3,   // [16,16]
               const float* __restrict__ b3,   // [16]
               const float* __restrict__ W4,   // [16,1]
               const float* __restrict__ b4,   // [1]
               float* __restrict__ out)        // [N]
{
    extern __shared__ float sm[];
    float* x0s  = sm;                 // [128][129]  x0 tile, later scalars
    float* as_  = sm + AS_OFF;        // [128][17]   embedding tile (padded)
    ull*   zad  = (ull*)(sm + ZAD_OFF); // [64][128] duplicated za pairs
    float* wb   = sm + WB_OFF;        // [64][128]   W chunk
    float* mids = sm + MID_OFF;       // [128][16]

    const int tid = threadIdx.x;
    const int n0  = blockIdx.x * BM;

    // ---- Stage x0 (first 128 cols) and a ----
    for (int t = tid; t < BM * 32; t += NTH) {
        int lr = t >> 5, c4 = (t & 31) << 2;
        float4 v = *(const float4*)(nv + (size_t)(n0 + lr) * DIN + c4);
        float* dst = x0s + lr * X0_PITCH + c4;
        dst[0] = v.x; dst[1] = v.y; dst[2] = v.z; dst[3] = v.w;
    }
    for (int t = tid; t < BM * 4; t += NTH) {
        int lr = t >> 2, c4 = (t & 3) << 2;
        float4 v = *(const float4*)(ae + (size_t)(n0 + lr) * AEMB + c4);
        float* dst = as_ + lr * AS_PITCH + c4;
        dst[0] = v.x; dst[1] = v.y; dst[2] = v.z; dst[3] = v.w;
    }

    // ---- Prefetch W chunk 0 into registers ----
    float4 wreg[8];
#pragma unroll
    for (int q = 0; q < 8; ++q) {
        int t = tid + q * NTH;               // 0..2047 float4 slots
        int row = t >> 5, c4 = (t & 31) << 2;   // row = i_loc*16 + a
        wreg[q] = *(const float4*)(W1 + (size_t)(row >> 4) * 3584
                                      + (row & 15) * OUT0D + c4);
    }

    // ---- Phase 1: s = za @ W1flat  (M=128, N=128, K=2048, chunks of 64) ----
    const int tx = tid & 15;      // k-group: k = tx*8 + 2q
    const int ty = tid >> 4;      // n-group: n = ty + 16r
    ull acc[8][4];
#pragma unroll
    for (int r = 0; r < 8; ++r)
#pragma unroll
        for (int q = 0; q < 4; ++q) acc[r][q] = 0ULL;

    for (int ic = 0; ic < NCHUNK; ++ic) {
        __syncthreads();   // previous GEMM done -> safe to overwrite zad/wb

        // store prefetched W chunk
#pragma unroll
        for (int q = 0; q < 8; ++q) {
            int t = tid + q * NTH;
            *(float4*)(wb + t * 4) = wreg[q];
        }
        // build duplicated za tile: kl = i_loc*16 + a, 8192 pairs
#pragma unroll
        for (int j = 0; j < 32; ++j) {
            int e  = tid + j * NTH;
            int kl = e >> 7, n = e & 127;
            int i  = ic * 4 + (kl >> 4);
            int aa = kl & 15;
            float z = x0s[n * X0_PITCH + i] * as_[n * AS_PITCH + aa];
            zad[kl * BM + n] = pk2(z, z);
        }
        // prefetch next W chunk
        if (ic + 1 < NCHUNK) {
            const float* src = W1 + (size_t)(ic + 1) * 4 * 16 * OUT0D;
#pragma unroll
            for (int q = 0; q < 8; ++q) {
                int t = tid + q * NTH;
                int row = t >> 5, c4 = (t & 31) << 2;
                wreg[q] = *(const float4*)(src + (size_t)(row >> 4) * 3584
                                               + (row & 15) * OUT0D + c4);
            }
        }
        __syncthreads();

        // GEMM on this chunk: pure fma2 inner loop
#pragma unroll 8
        for (int kk = 0; kk < KC; ++kk) {
            const ull* zrow = zad + kk * BM;
            const ull* wrow = (const ull*)(wb + kk * 128) + tx * 4;
            ull w[4];
#pragma unroll
            for (int q = 0; q < 4; ++q) w[q] = wrow[q];
            ull z[8];
#pragma unroll
            for (int r = 0; r < 8; ++r) z[r] = zrow[ty + 16 * r];
#pragma unroll
            for (int r = 0; r < 8; ++r)
#pragma unroll
                for (int q = 0; q < 4; ++q)
                    acc[r][q] = fma2(z[r], w[q], acc[r][q]);
        }
    }

    // ---- Epilogue 1: scalars = silu(s*INV + b1[k]) -> x0s ----
    const float INV = 0.022097086912079608f;   // 1/sqrt(128*16)
#pragma unroll
    for (int r = 0; r < 8; ++r) {
        int lr = ty + 16 * r;
#pragma unroll
        for (int q = 0; q < 4; ++q) {
            float lo, hi;
            upk2(acc[r][q], lo, hi);
            int k = tx * 8 + 2 * q;
            x0s[lr * X0_PITCH + k]     = silu_f(lo * INV + b1[k]);
            x0s[lr * X0_PITCH + k + 1] = silu_f(hi * INV + b1[k + 1]);
        }
    }

    // ---- Phase 2: mid[n,j] = (scal ⊗ a) @ W2flat * INV + b2 ----
    const int nd = tid >> 1;
    const int jh = tid & 1;
    ull aregd[16];
#pragma unroll
    for (int a = 0; a < 16; ++a) {
        float av = as_[nd * AS_PITCH + a];
        aregd[a] = pk2(av, av);
    }
    ull m2[4] = {0ULL, 0ULL, 0ULL, 0ULL};

    for (int ic2 = 0; ic2 < 8; ++ic2) {   // 8 chunks of 16 i's (16KB each)
        __syncthreads();
        for (int t = tid; t < 1024; t += NTH)
            *(float4*)(wb + t * 4) = *(const float4*)(W2 + (size_t)ic2 * 4096 + t * 4);
        __syncthreads();
#pragma unroll 2
        for (int ii = 0; ii < 16; ++ii) {
            float si = x0s[nd * X0_PITCH + ic2 * 16 + ii];
            ull ss = pk2(si, si);
#pragma unroll
            for (int a = 0; a < 16; ++a) {
                ull zz = mul2(ss, aregd[a]);
                const ull* wp = (const ull*)(wb + ii * 256 + a * 16 + jh * 8);
#pragma unroll
                for (int q = 0; q < 4; ++q) m2[q] = fma2(zz, wp[q], m2[q]);
            }
        }
    }
#pragma unroll
    for (int q = 0; q < 4; ++q) {
        float lo, hi;
        upk2(m2[q], lo, hi);
        int j = jh * 8 + 2 * q;
        mids[nd * AEMB + j]     = lo * INV + b2[j];
        mids[nd * AEMB + j + 1] = hi * INV + b2[j + 1];
    }
    __syncthreads();

    // ---- Phase 3: h = silu(mid @ W3 * 0.25 + b3); out = h @ W4 * 0.25 + b4 ----
    if (tid < BM) {
        float mv[16];
#pragma unroll
        for (int j = 0; j < 16; ++j) mv[j] = mids[tid * AEMB + j];
        float o = 0.0f;
#pragma unroll
        for (int jo = 0; jo < 16; ++jo) {
            float t = 0.0f;
#pragma unroll
            for (int ji = 0; ji < 16; ++ji) t += mv[ji] * W3[ji * 16 + jo];
            t = t * 0.25f + b3[jo];
            o += silu_f(t) * W4[jo];
        }
        out[n0 + tid] = o * 0.25f + b4[0];
    }
}

extern "C" void kernel_launch(void* const* d_in, const int* in_sizes, int n_in,
                              void* d_out, int out_size) {
    const float* nv = (const float*)d_in[0];
    const float* ae = (const float*)d_in[1];
    const float* W1 = (const float*)d_in[2];
    // d_in[3], d_in[4] dead (W1_l1, W1_l2)
    const float* b1 = (const float*)d_in[5];
    const float* W2 = (const float*)d_in[6];
    const float* b2 = (const float*)d_in[7];
    const float* W3 = (const float*)d_in[8];
    const float* b3 = (const float*)d_in[9];
    const float* W4 = (const float*)d_in[10];
    const float* b4 = (const float*)d_in[11];
    float* out = (float*)d_out;

    int nodes = in_sizes[1] / AEMB;
    int grid  = nodes / BM;

    cudaFuncSetAttribute(tp_head_kernel,
                         cudaFuncAttributeMaxDynamicSharedMemorySize, SMEM_BYTES);
    tp_head_kernel<<<grid, NTH, SMEM_BYTES>>>(nv, ae, W1, b1, W2, b2,
                                              W3, b3, W4, b4, out);
}

// round 3
// speedup vs baseline: 1.1298x; 1.1298x over previous
#include <cuda_runtime.h>
#include <math.h>

// Problem constants
#define AEMB   16
#define DIN    480
#define OUT0D  224     // W1_l0 last-dim stride (only k<128 live)
#define M0     128
#define BM     128     // nodes per CTA
#define NTH    256
#define KC     64      // K-chunk (4 i x 16 a)
#define NCHUNK 32      // 2048 / KC

// Shared memory layout (floats)
#define X0_PITCH 129
#define AS_PITCH 17
#define AS_OFF   (BM * X0_PITCH)                  // 16512
#define ZAD_OFF  (AS_OFF + BM * AS_PITCH)         // +2176  = 18688
#define WB_OFF   (ZAD_OFF + KC * BM * 2)          // +16384 = 35072
#define MID_OFF  (WB_OFF + KC * 128)              // +8192  = 43264
#define SMEM_FLOATS (MID_OFF + BM * AEMB)         // 45312
#define SMEM_BYTES  (SMEM_FLOATS * 4)             // 181248

typedef unsigned long long ull;

__device__ __forceinline__ ull pk2(float lo, float hi) {
    ull d; asm("mov.b64 %0, {%1, %2};" : "=l"(d) : "f"(lo), "f"(hi)); return d;
}
__device__ __forceinline__ ull fma2(ull a, ull b, ull c) {
    ull d; asm("fma.rn.f32x2 %0, %1, %2, %3;" : "=l"(d) : "l"(a), "l"(b), "l"(c)); return d;
}
__device__ __forceinline__ ull mul2(ull a, ull b) {
    ull d; asm("mul.rn.f32x2 %0, %1, %2;" : "=l"(d) : "l"(a), "l"(b)); return d;
}
__device__ __forceinline__ void upk2(ull v, float& lo, float& hi) {
    asm("mov.b64 {%0, %1}, %2;" : "=f"(lo), "=f"(hi) : "l"(v));
}
__device__ __forceinline__ float silu_f(float x) { return x / (1.0f + __expf(-x)); }

__global__ void __launch_bounds__(NTH, 1)
tp_head_kernel(const float* __restrict__ nv,   // node_vec   [N,480]
               const float* __restrict__ ae,   // embedding  [N,16]
               const float* __restrict__ W1,   // W1_l0      [128,16,224]
               const float* __restrict__ b1,   // [224]
               const float* __restrict__ W2,   // [128,16,16]
               const float* __restrict__ b2,   // [16]
               const float* __restrict__ W3,   // [16,16]
               const float* __restrict__ b3,   // [16]
               const float* __restrict__ W4,   // [16,1]
               const float* __restrict__ b4,   // [1]
               float* __restrict__ out)        // [N]
{
    extern __shared__ float sm[];
    float* x0s  = sm;                   // [128][129]  x0 tile, later scalars
    float* as_  = sm + AS_OFF;          // [128][17]   embedding tile
    ull*   zad  = (ull*)(sm + ZAD_OFF); // [64][128]   duplicated za pairs
    float* wb   = sm + WB_OFF;          // [64][128]   W chunk
    float* mids = sm + MID_OFF;         // [128][16]

    const int tid = threadIdx.x;
    const int n0  = blockIdx.x * BM;

    // ---- Stage x0 (first 128 cols) and a ----
    for (int t = tid; t < BM * 32; t += NTH) {
        int lr = t >> 5, c4 = (t & 31) << 2;
        float4 v = *(const float4*)(nv + (size_t)(n0 + lr) * DIN + c4);
        float* dst = x0s + lr * X0_PITCH + c4;
        dst[0] = v.x; dst[1] = v.y; dst[2] = v.z; dst[3] = v.w;
    }
    for (int t = tid; t < BM * 4; t += NTH) {
        int lr = t >> 2, c4 = (t & 3) << 2;
        float4 v = *(const float4*)(ae + (size_t)(n0 + lr) * AEMB + c4);
        float* dst = as_ + lr * AS_PITCH + c4;
        dst[0] = v.x; dst[1] = v.y; dst[2] = v.z; dst[3] = v.w;
    }

    // ---- Prefetch W chunk 0 into registers ----
    float4 wreg[8];
#pragma unroll
    for (int q = 0; q < 8; ++q) {
        int t = tid + q * NTH;                  // 0..2047 float4 slots
        int row = t >> 5, c4 = (t & 31) << 2;   // row = i_loc*16 + a
        wreg[q] = *(const float4*)(W1 + (size_t)(row >> 4) * 3584
                                      + (row & 15) * OUT0D + c4);
    }

    // ---- Phase 1: s = za @ W1flat  (M=128, N=128, K=2048, chunks of 64) ----
    // Thread owns nodes n = ty + 16r (r=0..7) and k-pairs p = tx + 16q (q=0..3),
    // i.e. k = 2(tx+16q)+{0,1}.  Lane-contiguous w loads -> conflict-free.
    const int tx = tid & 15;
    const int ty = tid >> 4;
    ull acc[8][4];
#pragma unroll
    for (int r = 0; r < 8; ++r)
#pragma unroll
        for (int q = 0; q < 4; ++q) acc[r][q] = 0ULL;

    for (int ic = 0; ic < NCHUNK; ++ic) {
        __syncthreads();   // previous GEMM done -> safe to overwrite zad/wb

        // store prefetched W chunk
#pragma unroll
        for (int q = 0; q < 8; ++q) {
            int t = tid + q * NTH;
            *(float4*)(wb + t * 4) = wreg[q];
        }
        // build duplicated za tile: kl = i_loc*16 + a
#pragma unroll
        for (int j = 0; j < 32; ++j) {
            int e  = tid + j * NTH;
            int kl = e >> 7, n = e & 127;
            int i  = ic * 4 + (kl >> 4);
            int aa = kl & 15;
            float z = x0s[n * X0_PITCH + i] * as_[n * AS_PITCH + aa];
            zad[kl * BM + n] = pk2(z, z);
        }
        // prefetch next W chunk
        if (ic + 1 < NCHUNK) {
            const float* src = W1 + (size_t)(ic + 1) * 4 * 16 * OUT0D;
#pragma unroll
            for (int q = 0; q < 8; ++q) {
                int t = tid + q * NTH;
                int row = t >> 5, c4 = (t & 31) << 2;
                wreg[q] = *(const float4*)(src + (size_t)(row >> 4) * 3584
                                               + (row & 15) * OUT0D + c4);
            }
        }
        __syncthreads();

        // GEMM on this chunk: pure fma2, conflict-free + broadcast LDS
#pragma unroll 8
        for (int kk = 0; kk < KC; ++kk) {
            const ull* zrow = zad + kk * BM;
            const ull* wrow = (const ull*)(wb + kk * 128);
            ull w[4];
#pragma unroll
            for (int q = 0; q < 4; ++q) w[q] = wrow[tx + 16 * q];
            ull z[8];
#pragma unroll
            for (int r = 0; r < 8; ++r) z[r] = zrow[ty + 16 * r];
#pragma unroll
            for (int r = 0; r < 8; ++r)
#pragma unroll
                for (int q = 0; q < 4; ++q)
                    acc[r][q] = fma2(z[r], w[q], acc[r][q]);
        }
    }

    // ---- Epilogue 1: scalars = silu(s*INV + b1[k]) -> x0s ----
    const float INV = 0.022097086912079608f;   // 1/sqrt(128*16)
#pragma unroll
    for (int r = 0; r < 8; ++r) {
        int lr = ty + 16 * r;
#pragma unroll
        for (int q = 0; q < 4; ++q) {
            float lo, hi;
            upk2(acc[r][q], lo, hi);
            int k = (tx + 16 * q) * 2;
            x0s[lr * X0_PITCH + k]     = silu_f(lo * INV + b1[k]);
            x0s[lr * X0_PITCH + k + 1] = silu_f(hi * INV + b1[k + 1]);
        }
    }

    // ---- Phase 2: mid[n,j] = (scal ⊗ a) @ W2flat * INV + b2 ----
    const int nd = tid >> 1;
    const int jh = tid & 1;
    ull aregd[16];
#pragma unroll
    for (int a = 0; a < 16; ++a) {
        float av = as_[nd * AS_PITCH + a];
        aregd[a] = pk2(av, av);
    }
    ull m2[4] = {0ULL, 0ULL, 0ULL, 0ULL};

    for (int ic2 = 0; ic2 < 8; ++ic2) {   // 8 chunks of 16 i's (16KB each)
        __syncthreads();
        for (int t = tid; t < 1024; t += NTH)
            *(float4*)(wb + t * 4) = *(const float4*)(W2 + (size_t)ic2 * 4096 + t * 4);
        __syncthreads();
#pragma unroll 2
        for (int ii = 0; ii < 16; ++ii) {
            float si = x0s[nd * X0_PITCH + ic2 * 16 + ii];
            ull ss = pk2(si, si);
#pragma unroll
            for (int a = 0; a < 16; ++a) {
                ull zz = mul2(ss, aregd[a]);
                const ull* wp = (const ull*)(wb + ii * 256 + a * 16 + jh * 8);
#pragma unroll
                for (int q = 0; q < 4; ++q) m2[q] = fma2(zz, wp[q], m2[q]);
            }
        }
    }
#pragma unroll
    for (int q = 0; q < 4; ++q) {
        float lo, hi;
        upk2(m2[q], lo, hi);
        int j = jh * 8 + 2 * q;
        mids[nd * AEMB + j]     = lo * INV + b2[j];
        mids[nd * AEMB + j + 1] = hi * INV + b2[j + 1];
    }
    __syncthreads();

    // ---- Phase 3: h = silu(mid @ W3 * 0.25 + b3); out = h @ W4 * 0.25 + b4 ----
    if (tid < BM) {
        float mv[16];
#pragma unroll
        for (int j = 0; j < 16; ++j) mv[j] = mids[tid * AEMB + j];
        float o = 0.0f;
#pragma unroll
        for (int jo = 0; jo < 16; ++jo) {
            float t = 0.0f;
#pragma unroll
            for (int ji = 0; ji < 16; ++ji) t += mv[ji] * W3[ji * 16 + jo];
            t = t * 0.25f + b3[jo];
            o += silu_f(t) * W4[jo];
        }
        out[n0 + tid] = o * 0.25f + b4[0];
    }
}

extern "C" void kernel_launch(void* const* d_in, const int* in_sizes, int n_in,
                              void* d_out, int out_size) {
    const float* nv = (const float*)d_in[0];
    const float* ae = (const float*)d_in[1];
    const float* W1 = (const float*)d_in[2];
    // d_in[3], d_in[4] dead (W1_l1, W1_l2)
    const float* b1 = (const float*)d_in[5];
    const float* W2 = (const float*)d_in[6];
    const float* b2 = (const float*)d_in[7];
    const float* W3 = (const float*)d_in[8];
    const float* b3 = (const float*)d_in[9];
    const float* W4 = (const float*)d_in[10];
    const float* b4 = (const float*)d_in[11];
    float* out = (float*)d_out;

    int nodes = in_sizes[1] / AEMB;
    int grid  = nodes / BM;

    cudaFuncSetAttribute(tp_head_kernel,
                         cudaFuncAttributeMaxDynamicSharedMemorySize, SMEM_BYTES);
    tp_head_kernel<<<grid, NTH, SMEM_BYTES>>>(nv, ae, W1, b1, W2, b2,
                                              W3, b3, W4, b4, out);
}

// round 5
// speedup vs baseline: 2.5464x; 2.2539x over previous
#include <cuda_runtime.h>
#include <math.h>

#define AEMB 16
#define DIN  480
#define NTH  256
#define BM   128

// ---- shared memory layout (float offsets) ----
#define X0_PITCH 129
#define AS_PITCH 17
#define AS_OFF   (BM * X0_PITCH)            // 16512
#define B1_OFF   (AS_OFF + BM * AS_PITCH)   // 18688
#define B2_OFF   (B1_OFF + 128)             // 18816
#define WB_OFF   (B2_OFF + 32)              // 18848 (even -> 8B aligned)
#define MID_OFF  (WB_OFF + 8192)            // 27040
#define SMEM_FLOATS (MID_OFF + BM * 17)     // 29216
#define SMEM_BYTES  (SMEM_FLOATS * 4)       // 116864

typedef unsigned long long ull;

__device__ __forceinline__ unsigned cvt_tf32(float f) {
    unsigned u; asm("cvt.rna.tf32.f32 %0, %1;" : "=r"(u) : "f"(f)); return u;
}
__device__ __forceinline__ void mma_tf32(float* d, unsigned a0, unsigned a1,
                                         unsigned a2, unsigned a3,
                                         unsigned b0, unsigned b1) {
    asm volatile(
        "mma.sync.aligned.m16n8k8.row.col.f32.tf32.tf32.f32 "
        "{%0,%1,%2,%3}, {%4,%5,%6,%7}, {%8,%9}, {%0,%1,%2,%3};"
        : "+f"(d[0]), "+f"(d[1]), "+f"(d[2]), "+f"(d[3])
        : "r"(a0), "r"(a1), "r"(a2), "r"(a3), "r"(b0), "r"(b1));
}
__device__ __forceinline__ void upkb(ull v, unsigned& lo, unsigned& hi) {
    asm("mov.b64 {%0, %1}, %2;" : "=r"(lo), "=r"(hi) : "l"(v));
}
__device__ __forceinline__ float silu_f(float x) { return x / (1.0f + __expf(-x)); }

__global__ void __launch_bounds__(NTH, 1)
tp_head_kernel(const float* __restrict__ nv, const float* __restrict__ ae,
               const float* __restrict__ W1, const float* __restrict__ b1,
               const float* __restrict__ W2, const float* __restrict__ b2,
               const float* __restrict__ W3, const float* __restrict__ b3,
               const float* __restrict__ W4, const float* __restrict__ b4,
               float* __restrict__ out)
{
    extern __shared__ float sm[];
    float* x0s  = sm;                 // [128][129] x0, later scalars
    float* as_  = sm + AS_OFF;        // [128][17]
    float* b1s  = sm + B1_OFF;        // [128]
    float* b2s  = sm + B2_OFF;        // [16]
    float* wb   = sm + WB_OFF;        // 8192 floats: B staging (pair layout)
    ull*   wbu  = (ull*)wb;
    float* mids = sm + MID_OFF;       // [128][17]

    const int tid = threadIdx.x;
    const int wid = tid >> 5;
    const int l   = tid & 31;
    const int n0  = blockIdx.x * BM;

    // MMA row ownership: lane l of warp wid owns rows r0, r1 of the CTA tile
    const int r0 = wid * 16 + (l >> 2);
    const int r1 = r0 + 8;
    const int lk = l & 3;             // k-within-chunk index
    const int lc = l >> 2;            // col-within-tile index

    // ---- stage x0 (first 128 cols), a, b1, b2 ----
    for (int t = tid; t < BM * 32; t += NTH) {
        int lr = t >> 5, c4 = (t & 31) << 2;
        float4 v = *(const float4*)(nv + (size_t)(n0 + lr) * DIN + c4);
        float* dst = x0s + lr * X0_PITCH + c4;
        dst[0] = v.x; dst[1] = v.y; dst[2] = v.z; dst[3] = v.w;
    }
    for (int t = tid; t < BM * 4; t += NTH) {
        int lr = t >> 2, c4 = (t & 3) << 2;
        float4 v = *(const float4*)(ae + (size_t)(n0 + lr) * AEMB + c4);
        float* dst = as_ + lr * AS_PITCH + c4;
        dst[0] = v.x; dst[1] = v.y; dst[2] = v.z; dst[3] = v.w;
    }
    if (tid < 128) b1s[tid] = b1[tid];
    if (tid >= 128 && tid < 144) b2s[tid - 128] = b2[tid - 128];

    // ---- prefetch W1 superchunk 0 (K=64 x 128 cols) ----
    float4 wreg[8];
    {
        int kl = tid & 63, grp = tid >> 6;
        int i = kl >> 4, aa = kl & 15;
        const float4* srcp = (const float4*)(W1 + ((size_t)i * 16 + aa) * 224);
#pragma unroll
        for (int j = 0; j < 8; ++j) wreg[j] = srcp[grp * 8 + j];
    }
    __syncthreads();

    // per-lane embedding registers for the two owned rows
    float a0r[16], a1r[16];
#pragma unroll
    for (int a = 0; a < 16; ++a) {
        a0r[a] = as_[r0 * AS_PITCH + a];
        a1r[a] = as_[r1 * AS_PITCH + a];
    }

    // =================== Phase 1: s = (x0 (x) a) @ W1flat ===================
    float acc[16][4];
#pragma unroll
    for (int t = 0; t < 16; ++t)
#pragma unroll
        for (int e = 0; e < 4; ++e) acc[t][e] = 0.0f;

    for (int sc = 0; sc < 32; ++sc) {
        // store prefetched W chunk -> pair layout, cvt to tf32
        {
            int kl = tid & 63, grp = tid >> 6;
            int kc = kl >> 3, krow = kl & 7;
            int base = kc * 1024 + (krow & 3) * 2 + (krow >> 2);
#pragma unroll
            for (int j = 0; j < 8; ++j) {
                int c0 = (grp * 8 + j) * 4;
                float v[4] = {wreg[j].x, wreg[j].y, wreg[j].z, wreg[j].w};
#pragma unroll
                for (int e = 0; e < 4; ++e)
                    *(unsigned*)(wb + base + (c0 + e) * 8) = cvt_tf32(v[e]);
            }
        }
        if (sc + 1 < 32) {
            int kl = tid & 63, grp = tid >> 6;
            int i = (sc + 1) * 4 + (kl >> 4), aa = kl & 15;
            const float4* srcp = (const float4*)(W1 + ((size_t)i * 16 + aa) * 224);
#pragma unroll
            for (int j = 0; j < 8; ++j) wreg[j] = srcp[grp * 8 + j];
        }
        __syncthreads();

#pragma unroll
        for (int kc = 0; kc < 8; ++kc) {
            int i = sc * 4 + (kc >> 1);
            int aa0 = (kc & 1) * 8;
            float x0v0 = x0s[r0 * X0_PITCH + i];
            float x0v1 = x0s[r1 * X0_PITCH + i];
            unsigned ua0 = cvt_tf32(x0v0 * a0r[aa0 + lk]);
            unsigned ua1 = cvt_tf32(x0v1 * a1r[aa0 + lk]);
            unsigned ua2 = cvt_tf32(x0v0 * a0r[aa0 + lk + 4]);
            unsigned ua3 = cvt_tf32(x0v1 * a1r[aa0 + lk + 4]);
            const ull* bp = wbu + kc * 512 + lc * 4 + lk;
#pragma unroll
            for (int t = 0; t < 16; ++t) {
                unsigned b0, b1v;
                upkb(bp[t * 32], b0, b1v);
                mma_tf32(acc[t], ua0, ua1, ua2, ua3, b0, b1v);
            }
        }
        __syncthreads();
    }

    // ---- epilogue 1: scalars = silu(s*INV + b1) -> x0s ----
    const float INV = 0.022097086912079608f;   // 1/sqrt(128*16)
#pragma unroll
    for (int t = 0; t < 16; ++t) {
        int c0 = t * 8 + lk * 2;
        x0s[r0 * X0_PITCH + c0]     = silu_f(acc[t][0] * INV + b1s[c0]);
        x0s[r0 * X0_PITCH + c0 + 1] = silu_f(acc[t][1] * INV + b1s[c0 + 1]);
        x0s[r1 * X0_PITCH + c0]     = silu_f(acc[t][2] * INV + b1s[c0]);
        x0s[r1 * X0_PITCH + c0 + 1] = silu_f(acc[t][3] * INV + b1s[c0 + 1]);
    }

    // =================== Phase 2: mid = (scal (x) a) @ W2flat ===================
    float4 w2reg;
    {
        int kl = tid >> 2, j4 = (tid & 3) * 4;
        w2reg = *(const float4*)(W2 + (size_t)kl * 16 + j4);
    }
    float acc2[2][4];
#pragma unroll
    for (int t = 0; t < 2; ++t)
#pragma unroll
        for (int e = 0; e < 4; ++e) acc2[t][e] = 0.0f;

    for (int sc = 0; sc < 32; ++sc) {
        __syncthreads();   // previous wb consumers done / epilogue-1 visible
        {
            int kl = tid >> 2, j4 = (tid & 3) * 4;
            int kc = kl >> 3, krow = kl & 7;
            int base = kc * 128 + (krow & 3) * 2 + (krow >> 2);
            float v[4] = {w2reg.x, w2reg.y, w2reg.z, w2reg.w};
#pragma unroll
            for (int e = 0; e < 4; ++e)
                *(unsigned*)(wb + base + (j4 + e) * 8) = cvt_tf32(v[e]);
        }
        if (sc + 1 < 32) {
            int kl = tid >> 2, j4 = (tid & 3) * 4;
            w2reg = *(const float4*)(W2 + ((size_t)(sc + 1) * 64 + kl) * 16 + j4);
        }
        __syncthreads();

#pragma unroll
        for (int kc = 0; kc < 8; ++kc) {
            int i = sc * 4 + (kc >> 1);
            int aa0 = (kc & 1) * 8;
            float sv0 = x0s[r0 * X0_PITCH + i];
            float sv1 = x0s[r1 * X0_PITCH + i];
            unsigned ua0 = cvt_tf32(sv0 * a0r[aa0 + lk]);
            unsigned ua1 = cvt_tf32(sv1 * a1r[aa0 + lk]);
            unsigned ua2 = cvt_tf32(sv0 * a0r[aa0 + lk + 4]);
            unsigned ua3 = cvt_tf32(sv1 * a1r[aa0 + lk + 4]);
            const ull* bp = wbu + kc * 64 + lc * 4 + lk;
#pragma unroll
            for (int t = 0; t < 2; ++t) {
                unsigned b0, b1v;
                upkb(bp[t * 32], b0, b1v);
                mma_tf32(acc2[t], ua0, ua1, ua2, ua3, b0, b1v);
            }
        }
    }
    // epilogue 2: mid -> mids (no activation)
#pragma unroll
    for (int t = 0; t < 2; ++t) {
        int c0 = t * 8 + lk * 2;
        mids[r0 * 17 + c0]     = acc2[t][0] * INV + b2s[c0];
        mids[r0 * 17 + c0 + 1] = acc2[t][1] * INV + b2s[c0 + 1];
        mids[r1 * 17 + c0]     = acc2[t][2] * INV + b2s[c0];
        mids[r1 * 17 + c0 + 1] = acc2[t][3] * INV + b2s[c0 + 1];
    }
    __syncthreads();

    // stage W3/W4/b3/b4 into wb (free now)
    if (tid < 256) wb[tid] = W3[tid];
    if (tid < 16)  { wb[256 + tid] = W4[tid]; wb[272 + tid] = b3[tid]; }
    if (tid == 0)  wb[288] = b4[0];
    __syncthreads();

    // =================== Phase 3: tiny 16x16 head ===================
    if (tid < BM) {
        float mv[16];
#pragma unroll
        for (int j = 0; j < 16; ++j) mv[j] = mids[tid * 17 + j];
        float o = 0.0f;
#pragma unroll
        for (int jo = 0; jo < 16; ++jo) {
            float t = 0.0f;
#pragma unroll
            for (int ji = 0; ji < 16; ++ji) t += mv[ji] * wb[ji * 16 + jo];
            t = t * 0.25f + wb[272 + jo];
            o += silu_f(t) * wb[256 + jo];
        }
        out[n0 + tid] = o * 0.25f + wb[288];
    }
}

extern "C" void kernel_launch(void* const* d_in, const int* in_sizes, int n_in,
                              void* d_out, int out_size) {
    const float* nv = (const float*)d_in[0];
    const float* ae = (const float*)d_in[1];
    const float* W1 = (const float*)d_in[2];
    // d_in[3], d_in[4] dead (W1_l1, W1_l2)
    const float* b1 = (const float*)d_in[5];
    const float* W2 = (const float*)d_in[6];
    const float* b2 = (const float*)d_in[7];
    const float* W3 = (const float*)d_in[8];
    const float* b3 = (const float*)d_in[9];
    const float* W4 = (const float*)d_in[10];
    const float* b4 = (const float*)d_in[11];
    float* out = (float*)d_out;

    int nodes = in_sizes[1] / AEMB;
    int grid  = nodes / BM;

    cudaFuncSetAttribute(tp_head_kernel,
                         cudaFuncAttributeMaxDynamicSharedMemorySize, SMEM_BYTES);
    tp_head_kernel<<<grid, NTH, SMEM_BYTES>>>(nv, ae, W1, b1, W2, b2,
                                              W3, b3, W4, b4, out);
}

// round 6
// speedup vs baseline: 2.8927x; 1.1360x over previous
#include <cuda_runtime.h>
#include <math.h>

#define AEMB 16
#define DIN  480
#define NTH  512
#define BM   128

// ---- shared memory layout (float offsets) ----
#define X0_PITCH 129
#define AS_PITCH 17
#define AS_OFF   (BM * X0_PITCH)            // 16512
#define B1_OFF   (AS_OFF + BM * AS_PITCH)   // 18688
#define B2_OFF   (B1_OFF + 128)             // 18816
#define WB_OFF   (B2_OFF + 16)              // 18832 (16B-aligned: *4)
#define WBUF     8256                       // 8 kc-blocks * 1032 (1024 + 8 skew)
#define MID_OFF  (WB_OFF + 2 * WBUF)        // 35344
#define SMEM_FLOATS (MID_OFF + BM * 17)     // 37520
#define SMEM_BYTES  (SMEM_FLOATS * 4)       // 150080

__device__ __forceinline__ unsigned cvt_tf32(float f) {
    unsigned u; asm("cvt.rna.tf32.f32 %0, %1;" : "=r"(u) : "f"(f)); return u;
}
__device__ __forceinline__ void mma_tf32(float* d, unsigned a0, unsigned a1,
                                         unsigned a2, unsigned a3,
                                         unsigned b0, unsigned b1) {
    asm volatile(
        "mma.sync.aligned.m16n8k8.row.col.f32.tf32.tf32.f32 "
        "{%0,%1,%2,%3}, {%4,%5,%6,%7}, {%8,%9}, {%0,%1,%2,%3};"
        : "+f"(d[0]), "+f"(d[1]), "+f"(d[2]), "+f"(d[3])
        : "r"(a0), "r"(a1), "r"(a2), "r"(a3), "r"(b0), "r"(b1));
}
__device__ __forceinline__ float silu_f(float x) { return x / (1.0f + __expf(-x)); }

__global__ void __launch_bounds__(NTH, 1)
tp_head_kernel(const float* __restrict__ nv, const float* __restrict__ ae,
               const float* __restrict__ W1, const float* __restrict__ b1,
               const float* __restrict__ W2, const float* __restrict__ b2,
               const float* __restrict__ W3, const float* __restrict__ b3,
               const float* __restrict__ W4, const float* __restrict__ b4,
               float* __restrict__ out)
{
    extern __shared__ float sm[];
    float* x0s  = sm;                 // [128][129] x0, later scalars
    float* as_  = sm + AS_OFF;        // [128][17]
    float* b1s  = sm + B1_OFF;
    float* b2s  = sm + B2_OFF;
    float* wb   = sm + WB_OFF;        // 2 x WBUF B-staging buffers
    float* mids = sm + MID_OFF;       // [128][17]

    const int tid = threadIdx.x;
    const int wid = tid >> 5;
    const int l   = tid & 31;
    const int n0  = blockIdx.x * BM;
    const int q   = l >> 2;           // 0..7
    const int lk  = l & 3;            // 0..3

    // ---- stage x0 (first 128 cols), a, b1, b2 ----
    for (int t = tid; t < BM * 32; t += NTH) {
        int lr = t >> 5, c4 = (t & 31) << 2;
        float4 v = *(const float4*)(nv + (size_t)(n0 + lr) * DIN + c4);
        float* dst = x0s + lr * X0_PITCH + c4;
        dst[0] = v.x; dst[1] = v.y; dst[2] = v.z; dst[3] = v.w;
    }
    {
        int lr = tid >> 2, c4 = (tid & 3) << 2;  // 512 = 128*4 exactly
        float4 v = *(const float4*)(ae + (size_t)(n0 + lr) * AEMB + c4);
        float* dst = as_ + lr * AS_PITCH + c4;
        dst[0] = v.x; dst[1] = v.y; dst[2] = v.z; dst[3] = v.w;
    }
    if (tid < 128) b1s[tid] = b1[tid];
    if (tid >= 128 && tid < 144) b2s[tid - 128] = b2[tid - 128];

    // ---- phase-1 staging thread mapping ----
    const int cg1 = tid >> 6;        // column group (16 cols), = tp
    const int kl1 = tid & 63;        // k-row within 64-chunk
    const int kc1 = kl1 >> 3, kr1 = kl1 & 7;
    const int lk1 = kr1 & 3, hf1 = kr1 >> 2;
    float* st1base = wb + kc1 * 1032 + cg1 * 128;

    float4 wreg[4];
    {   // prefetch chunk 0
        const float* src = W1 + ((size_t)((kl1 >> 4) * 16 + (kl1 & 15))) * 224 + cg1 * 16;
#pragma unroll
        for (int j = 0; j < 4; ++j) wreg[j] = ((const float4*)src)[j];
    }
    __syncthreads();

    // ---- per-warp MMA geometry: 32 rows (2 strips) x 4 tiles ----
    const int rp = wid >> 2;          // row-pair 0..3 -> rows [rp*32, rp*32+32)
    const int nq = wid & 3;           // tile quad: tiles nq*4..nq*4+3
    float ar[4][4];                   // a[row_j, {lk, lk+4, 8+lk, 12+lk}]
#pragma unroll
    for (int j = 0; j < 4; ++j) {
        int rj = rp * 32 + q + j * 8;
        ar[j][0] = as_[rj * AS_PITCH + lk];
        ar[j][1] = as_[rj * AS_PITCH + lk + 4];
        ar[j][2] = as_[rj * AS_PITCH + lk + 8];
        ar[j][3] = as_[rj * AS_PITCH + lk + 12];
    }

    float acc[8][4];                  // [strip*4 + tile][frag]
#pragma unroll
    for (int t = 0; t < 8; ++t)
#pragma unroll
        for (int e = 0; e < 4; ++e) acc[t][e] = 0.0f;

    // =================== Phase 1: s = (x0 (x) a) @ W1flat ===================
    for (int sc = 0; sc < 32; ++sc) {
        {   // store wreg (chunk sc) -> buf, conflict-free skewed layout
            float* b = st1base + (sc & 1) * WBUF;
            const float* w = (const float*)wreg;
#pragma unroll
            for (int e = 0; e < 16; ++e)
                *(unsigned*)(b + ((e & 7) * 4 + lk1) * 4 + (e >> 3) * 2 + hf1) =
                    cvt_tf32(w[e]);
        }
        if (sc + 1 < 32) {  // prefetch chunk sc+1
            const float* src = W1 +
                ((size_t)(((sc + 1) * 4 + (kl1 >> 4)) * 16 + (kl1 & 15))) * 224 + cg1 * 16;
#pragma unroll
            for (int j = 0; j < 4; ++j) wreg[j] = ((const float4*)src)[j];
        }
        __syncthreads();

        const float* bbase = wb + (sc & 1) * WBUF;
        float xv[4];
#pragma unroll
        for (int kc = 0; kc < 8; ++kc) {
            if ((kc & 1) == 0) {
                int i = sc * 4 + (kc >> 1);
#pragma unroll
                for (int j = 0; j < 4; ++j)
                    xv[j] = x0s[(rp * 32 + q + j * 8) * X0_PITCH + i];
            }
            const int idx0 = (kc & 1) * 2;
            unsigned A0[4], A1[4];
            A0[0] = cvt_tf32(xv[0] * ar[0][idx0]);
            A0[1] = cvt_tf32(xv[1] * ar[1][idx0]);
            A0[2] = cvt_tf32(xv[0] * ar[0][idx0 + 1]);
            A0[3] = cvt_tf32(xv[1] * ar[1][idx0 + 1]);
            A1[0] = cvt_tf32(xv[2] * ar[2][idx0]);
            A1[1] = cvt_tf32(xv[3] * ar[3][idx0]);
            A1[2] = cvt_tf32(xv[2] * ar[2][idx0 + 1]);
            A1[3] = cvt_tf32(xv[3] * ar[3][idx0 + 1]);
#pragma unroll
            for (int j = 0; j < 2; ++j) {
                float4 bv = *((const float4*)(bbase + kc * 1032 + (nq * 2 + j) * 128) + l);
                unsigned b00 = __float_as_uint(bv.x), b01 = __float_as_uint(bv.y);
                unsigned b10 = __float_as_uint(bv.z), b11 = __float_as_uint(bv.w);
                mma_tf32(acc[j * 2 + 0],     A0[0], A0[1], A0[2], A0[3], b00, b01);
                mma_tf32(acc[j * 2 + 1],     A0[0], A0[1], A0[2], A0[3], b10, b11);
                mma_tf32(acc[4 + j * 2 + 0], A1[0], A1[1], A1[2], A1[3], b00, b01);
                mma_tf32(acc[4 + j * 2 + 1], A1[0], A1[1], A1[2], A1[3], b10, b11);
            }
        }
    }
    __syncthreads();   // all warps done reading x0s before scalars overwrite it

    // ---- epilogue 1: scalars = silu(s*INV + b1) -> x0s ----
    const float INV = 0.022097086912079608f;   // 1/sqrt(128*16)
#pragma unroll
    for (int st = 0; st < 2; ++st)
#pragma unroll
        for (int tt = 0; tt < 4; ++tt) {
            int c0 = (nq * 4 + tt) * 8 + lk * 2;
            int row = rp * 32 + st * 16 + q;
            float* a = acc[st * 4 + tt];
            x0s[row * X0_PITCH + c0]           = silu_f(a[0] * INV + b1s[c0]);
            x0s[row * X0_PITCH + c0 + 1]       = silu_f(a[1] * INV + b1s[c0 + 1]);
            x0s[(row + 8) * X0_PITCH + c0]     = silu_f(a[2] * INV + b1s[c0]);
            x0s[(row + 8) * X0_PITCH + c0 + 1] = silu_f(a[3] * INV + b1s[c0 + 1]);
        }

    // ---- phase-2 staging mapping (chunks of 256 k-rows, 8 chunks) ----
    const int cg2 = tid >> 8;         // 0..1 (8 cols each)
    const int kl2 = tid & 255;
    const int kc2 = kl2 >> 3, kr2 = kl2 & 7;
    const int lk2 = kr2 & 3, hf2 = kr2 >> 2;
    float4 w2reg[2];
    {   // prefetch chunk 0
        const float* src = W2 + ((size_t)((kl2 >> 4) * 16 + (kl2 & 15))) * 16 + cg2 * 8;
        w2reg[0] = ((const float4*)src)[0];
        w2reg[1] = ((const float4*)src)[1];
    }
    __syncthreads();

    // ---- phase-2 MMA geometry: 16 rows x 1 tile per warp ----
    const int sW = wid >> 1;          // strip 0..7
    const int th = wid & 1;           // tile 0..1
    float ar2[2][4];
#pragma unroll
    for (int j = 0; j < 2; ++j) {
        int rj = sW * 16 + q + j * 8;
        ar2[j][0] = as_[rj * AS_PITCH + lk];
        ar2[j][1] = as_[rj * AS_PITCH + lk + 4];
        ar2[j][2] = as_[rj * AS_PITCH + lk + 8];
        ar2[j][3] = as_[rj * AS_PITCH + lk + 12];
    }
    float acc2[4] = {0.0f, 0.0f, 0.0f, 0.0f};

    for (int cN = 0; cN < 8; ++cN) {
        {   // store chunk cN
            float* b = wb + (cN & 1) * WBUF + kc2 * 136;
            const float* w = (const float*)w2reg;
#pragma unroll
            for (int e = 0; e < 8; ++e)
                *(unsigned*)(b + (e * 4 + lk2) * 4 + cg2 * 2 + hf2) = cvt_tf32(w[e]);
        }
        if (cN + 1 < 8) {
            const float* src = W2 +
                ((size_t)(((cN + 1) * 16 + (kl2 >> 4)) * 16 + (kl2 & 15))) * 16 + cg2 * 8;
            w2reg[0] = ((const float4*)src)[0];
            w2reg[1] = ((const float4*)src)[1];
        }
        __syncthreads();

        const float* bbase = wb + (cN & 1) * WBUF;
        float xv2[2];
#pragma unroll 8
        for (int kc = 0; kc < 32; ++kc) {
            if ((kc & 1) == 0) {
                int i = cN * 16 + (kc >> 1);
                xv2[0] = x0s[(sW * 16 + q) * X0_PITCH + i];
                xv2[1] = x0s[(sW * 16 + 8 + q) * X0_PITCH + i];
            }
            const int idx0 = (kc & 1) * 2;
            unsigned a0 = cvt_tf32(xv2[0] * ar2[0][idx0]);
            unsigned a1 = cvt_tf32(xv2[1] * ar2[1][idx0]);
            unsigned a2 = cvt_tf32(xv2[0] * ar2[0][idx0 + 1]);
            unsigned a3 = cvt_tf32(xv2[1] * ar2[1][idx0 + 1]);
            float2 bv = *(const float2*)(bbase + kc * 136 + l * 4 + th * 2);
            mma_tf32(acc2, a0, a1, a2, a3,
                     __float_as_uint(bv.x), __float_as_uint(bv.y));
        }
    }
    // epilogue 2
    {
        int c0 = th * 8 + lk * 2;
        int row = sW * 16 + q;
        mids[row * 17 + c0]           = acc2[0] * INV + b2s[c0];
        mids[row * 17 + c0 + 1]       = acc2[1] * INV + b2s[c0 + 1];
        mids[(row + 8) * 17 + c0]     = acc2[2] * INV + b2s[c0];
        mids[(row + 8) * 17 + c0 + 1] = acc2[3] * INV + b2s[c0 + 1];
    }
    __syncthreads();

    // stage W3/W4/b3/b4 into wb (free now)
    if (tid < 256) wb[tid] = W3[tid];
    if (tid >= 256 && tid < 272) wb[tid] = W4[tid - 256];
    if (tid >= 288 && tid < 304) wb[tid] = b3[tid - 288];
    if (tid == 304) wb[304] = b4[0];
    __syncthreads();

    // =================== Phase 3: tiny 16x16 head ===================
    if (tid < BM) {
        float mv[16];
#pragma unroll
        for (int j = 0; j < 16; ++j) mv[j] = mids[tid * 17 + j];
        float o = 0.0f;
#pragma unroll
        for (int jo = 0; jo < 16; ++jo) {
            float t = 0.0f;
#pragma unroll
            for (int ji = 0; ji < 16; ++ji) t += mv[ji] * wb[ji * 16 + jo];
            t = t * 0.25f + wb[288 + jo];
            o += silu_f(t) * wb[256 + jo];
        }
        out[n0 + tid] = o * 0.25f + wb[304];
    }
}

extern "C" void kernel_launch(void* const* d_in, const int* in_sizes, int n_in,
                              void* d_out, int out_size) {
    const float* nv = (const float*)d_in[0];
    const float* ae = (const float*)d_in[1];
    const float* W1 = (const float*)d_in[2];
    // d_in[3], d_in[4] dead (W1_l1, W1_l2)
    const float* b1 = (const float*)d_in[5];
    const float* W2 = (const float*)d_in[6];
    const float* b2 = (const float*)d_in[7];
    const float* W3 = (const float*)d_in[8];
    const float* b3 = (const float*)d_in[9];
    const float* W4 = (const float*)d_in[10];
    const float* b4 = (const float*)d_in[11];
    float* out = (float*)d_out;

    int nodes = in_sizes[1] / AEMB;
    int grid  = nodes / BM;

    cudaFuncSetAttribute(tp_head_kernel,
                         cudaFuncAttributeMaxDynamicSharedMemorySize, SMEM_BYTES);
    tp_head_kernel<<<grid, NTH, SMEM_BYTES>>>(nv, ae, W1, b1, W2, b2,
                                              W3, b3, W4, b4, out);
}